// round 17
// baseline (speedup 1.0000x reference)
#include <cuda_runtime.h>
#include <cuda_fp16.h>
#include <math.h>
#include <float.h>

#define NP    2048
#define MAXNP 256

// ---- shared memory layout (float offsets) ----
#define H1F     0            // fp16 H1: 128 rows x 144B (72 halfs) = 4608 floats
#define H1ROWH  72
#define H2F     4608         // fp16 H2: 128 rows x 272B (136 halfs) = 8704 floats
#define H2ROWH  136
#define W2SF    13312        // fp16 W2 row-major [128 ch][72 halfs] = 4608 floats
#define W2ROWH  72
#define OFF_WH    17920      // 7*256
#define OFF_BH    19712      // 8
#define OFF_FEATS 19720      // 256
#define OFF_PTS   19976      // 768 floats, 16B aligned
#define OFF_STAT  20744      // S1, S2, b1max, b2max
#define OFF_WPM   20748      // 8 per-warp point abs-max
#define SMEM_FLOATS 20760    // 83,040 bytes/CTA -> 2 CTAs/SM

extern __shared__ float s[];

__device__ unsigned g_ticket;
__global__ void reset_ticket_kernel() { g_ticket = 0u; }

__device__ __forceinline__ unsigned pack_h2(float lo, float hi) {
    unsigned u; asm("cvt.rn.f16x2.f32 %0, %1, %2;" : "=r"(u) : "f"(hi), "f"(lo)); return u;
}
__device__ __forceinline__ unsigned smem_addr_u32(const void* p) {
    unsigned r;
    asm("{ .reg .u64 t; cvta.to.shared.u64 t, %1; cvt.u32.u64 %0, t; }" : "=r"(r) : "l"(p));
    return r;
}
__device__ __forceinline__ void mma16(float& c0, float& c1, float& c2, float& c3,
                                      unsigned a0, unsigned a1, unsigned a2, unsigned a3,
                                      unsigned b0, unsigned b1) {
    asm("mma.sync.aligned.m16n8k16.row.col.f32.f16.f16.f32 "
        "{%0,%1,%2,%3}, {%4,%5,%6,%7}, {%8,%9}, {%0,%1,%2,%3};"
        : "+f"(c0), "+f"(c1), "+f"(c2), "+f"(c3)
        : "r"(a0), "r"(a1), "r"(a2), "r"(a3), "r"(b0), "r"(b1));
}
__device__ __forceinline__ void ldsm4(unsigned& r0, unsigned& r1, unsigned& r2, unsigned& r3,
                                      unsigned addr) {
    asm volatile("ldmatrix.sync.aligned.m8n8.x4.shared.b16 {%0,%1,%2,%3}, [%4];"
                 : "=r"(r0), "=r"(r1), "=r"(r2), "=r"(r3) : "r"(addr));
}

__global__ __launch_bounds__(256, 2)
void refine_kernel(const float* __restrict__ points,
                   const int*   __restrict__ counts,
                   const float* __restrict__ proposals,
                   const float* __restrict__ W1, const float* __restrict__ b1,
                   const float* __restrict__ W2, const float* __restrict__ b2,
                   const float* __restrict__ W3, const float* __restrict__ b3,
                   const float* __restrict__ Wc, const float* __restrict__ bc,
                   const float* __restrict__ Wr, const float* __restrict__ br,
                   float* __restrict__ out)
{
    __half* h1h = (__half*)(s + H1F);
    __half* h2h = (__half*)(s + H2F);
    __half* w2s = (__half*)(s + W2SF);
    __shared__ unsigned s_pid[2];
    __shared__ float    s_prop[6];
    __shared__ int      s_ncnt;

    const int tid  = threadIdx.x;
    const int w    = tid >> 5;           // warp 0..7
    const int lane = tid & 31;
    const int g    = lane >> 2;
    const int tq   = lane & 3;
    const unsigned smem_u32 = smem_addr_u32(s);

    // ---- init: W2 fp16 smem copy, head weights, stats partials ----
    for (int i = tid; i < 128 * 64; i += 256) {
        const int ch = i >> 6, k = i & 63;
        w2s[ch * W2ROWH + k] = __float2half(W2[k * 128 + ch]);
    }
    {   // head weights (256 threads = 256 channels)
        s[OFF_WH + tid] = Wc[tid];
        #pragma unroll
        for (int j = 0; j < 6; j++) s[OFF_WH + (1 + j) * 256 + tid] = Wr[tid * 6 + j];
    }
    if (tid == 0) s[OFF_BH] = bc[0];
    if (tid >= 1 && tid < 7) s[OFF_BH + tid] = br[tid - 1];
    {   // |W2| column-sum partials in H1 scratch
        const int j = tid & 127, c = tid >> 7;   // c in {0,1}, 32 ks each
        float pv = 0.0f;
        for (int k = 32 * c; k < 32 * c + 32; k++) pv += fabsf(W2[k * 128 + j]);
        s[tid] = pv;
    }
    __syncthreads();
    if (tid < 128) s[512 + tid] = s[tid] + s[128 + tid];
    if (tid >= 128 && tid < 192) {
        const int c = tid - 128;
        s[640 + c] = fabsf(W1[c]) + fabsf(W1[64 + c]) + fabsf(W1[128 + c]);
    }
    if (tid >= 192 && tid < 256) s[704 + (tid - 192)] = fabsf(b1[tid - 192]);
    __syncthreads();
    if (tid < 128) s[768 + tid] = fabsf(b2[tid]);

    // ---- W3 fp16 A-fragments (64 regs): warp owns channels [32w, 32w+32), cs halves ----
    unsigned a3h[64];
    #pragma unroll
    for (int cs = 0; cs < 2; cs++) {
        const int chw = 32 * w + 16 * cs;
        const int ca = chw + g, cb = chw + g + 8;
        #pragma unroll
        for (int ks = 0; ks < 8; ks++) {
            const int k0 = 16 * ks;
            a3h[32 * cs + 4 * ks + 0] = pack_h2(W3[(k0 + 2 * tq) * 256 + ca], W3[(k0 + 2 * tq + 1) * 256 + ca]);
            a3h[32 * cs + 4 * ks + 1] = pack_h2(W3[(k0 + 2 * tq) * 256 + cb], W3[(k0 + 2 * tq + 1) * 256 + cb]);
            a3h[32 * cs + 4 * ks + 2] = pack_h2(W3[(k0 + 2 * tq + 8) * 256 + ca], W3[(k0 + 2 * tq + 9) * 256 + ca]);
            a3h[32 * cs + 4 * ks + 3] = pack_h2(W3[(k0 + 2 * tq + 8) * 256 + cb], W3[(k0 + 2 * tq + 9) * 256 + cb]);
        }
    }
    __syncthreads();
    if (tid == 0) {
        float S2 = 0, S1 = 0, b1m = 0, b2m = 0;
        for (int i = 0; i < 128; i++) S2 = fmaxf(S2, s[512 + i]);
        for (int i = 0; i < 64;  i++) S1 = fmaxf(S1, s[640 + i]);
        for (int i = 0; i < 64;  i++) b1m = fmaxf(b1m, s[704 + i]);
        for (int i = 0; i < 128; i++) b2m = fmaxf(b2m, s[768 + i]);
        s[OFF_STAT + 0] = S1; s[OFF_STAT + 1] = S2;
        s[OFF_STAT + 2] = b1m; s[OFF_STAT + 3] = b2m;
        s_pid[0] = atomicAdd(&g_ticket, 1u);
    }
    __syncthreads();

    const int ch2 = 16 * w + g;                  // layer-2 channels (8 warps x 16)
    const float bb2a = b2[ch2];
    const float bb2b = b2[ch2 + 8];
    // ldmatrix bases
    const int lrow = 8 * (lane >> 4) + (lane & 7);
    const unsigned lm3off = smem_u32 + (unsigned)(H2F * 4) + (unsigned)(lrow * 272 + ((lane >> 3) & 1) * 16);
    const unsigned lm2off = smem_u32 + (unsigned)(lrow * 144 + ((lane >> 3) & 1) * 16);
    const unsigned aw2    = smem_u32 + (unsigned)(W2SF * 4)
                          + (unsigned)((16 * w + (lane & 15)) * 144 + (lane >> 4) * 16);

    {   // prologue: stage first proposal (all warps, per-warp abs-max slots)
        const unsigned pid0 = s_pid[0];
        if (pid0 < NP) {
            if (tid == 0) s_ncnt = counts[pid0];
            if (tid >= 32 && tid < 38) s_prop[tid - 32] = proposals[pid0 * 6 + (tid - 32)];
            const int nn = counts[pid0];
            const uint4* gp4 = (const uint4*)(points + (size_t)pid0 * (MAXNP * 3));
            uint4* sp4 = (uint4*)(s + OFF_PTS);
            const int nf4 = (3 * nn + 3) >> 2;
            float lm = 0.0f;
            for (int i = tid; i < nf4; i += 256) {
                const uint4 d = __ldg(gp4 + i);
                sp4[i] = d;
                lm = fmaxf(lm, fmaxf(fmaxf(fabsf(__uint_as_float(d.x)), fabsf(__uint_as_float(d.y))),
                                     fmaxf(fabsf(__uint_as_float(d.z)), fabsf(__uint_as_float(d.w)))));
            }
            #pragma unroll
            for (int o = 16; o > 0; o >>= 1) lm = fmaxf(lm, __shfl_xor_sync(0xffffffffu, lm, o));
            if (lane == 0) s[OFF_WPM + w] = lm;
        }
    }
    __syncthreads();

    // layer-1: reads proposal constants from s_prop each call (saves registers)
    auto do_l1 = [&](float sc1, int base, int cnt8) {
        const float cen0 = s_prop[0], cen1 = s_prop[1], cen2 = s_prop[2];
        const float is0 = 1.0f / (fabsf(s_prop[3]) + 1e-6f);
        const float is1 = 1.0f / (fabsf(s_prop[4]) + 1e-6f);
        const float is2 = 1.0f / (fabsf(s_prop[5]) + 1e-6f);
        for (int i = tid; i < cnt8 * 16; i += 256) {
            const int p = i >> 4, j = i & 15;
            const int c = 4 * j;
            const float* pt = s + OFF_PTS + (base + p) * 3;
            const float x0 = (pt[0] - cen0) * is0;
            const float x1 = (pt[1] - cen1) * is1;
            const float x2 = (pt[2] - cen2) * is2;
            float h0  = fmaf(x2, W1[128 + c],     fmaf(x1, W1[64 + c],     fmaf(x0, W1[c],     b1[c])));
            float h1v = fmaf(x2, W1[128 + c + 1], fmaf(x1, W1[64 + c + 1], fmaf(x0, W1[c + 1], b1[c + 1])));
            float h2v = fmaf(x2, W1[128 + c + 2], fmaf(x1, W1[64 + c + 2], fmaf(x0, W1[c + 2], b1[c + 2])));
            float h3v = fmaf(x2, W1[128 + c + 3], fmaf(x1, W1[64 + c + 3], fmaf(x0, W1[c + 3], b1[c + 3])));
            uint2 v;
            v.x = pack_h2(fmaxf(h0, 0.0f) * sc1, fmaxf(h1v, 0.0f) * sc1);
            v.y = pack_h2(fmaxf(h2v, 0.0f) * sc1, fmaxf(h3v, 0.0f) * sc1);
            *(uint2*)(h1h + p * H1ROWH + c) = v;
        }
    };

    int par = 0;
    for (;;) {
        const unsigned pid = s_pid[par];
        if (pid >= NP) break;
        if (tid == 0) s_pid[par ^ 1] = atomicAdd(&g_ticket, 1u);
        const int n = s_ncnt;
        const bool valid = (n >= 4);

        float chmax[2][2] = {{-FLT_MAX, -FLT_MAX}, {-FLT_MAX, -FLT_MAX}};
        float inv2 = 1.0f;

        if (valid) {
            // fp16 overflow guards (all threads compute redundantly)
            float sc1 = 1.0f, inv1 = 1.0f, sc2 = 1.0f;
            {
                float ptm = s[OFF_WPM];
                #pragma unroll
                for (int i = 1; i < 8; i++) ptm = fmaxf(ptm, s[OFF_WPM + i]);
                const float cmax = fmaxf(fabsf(s_prop[0]), fmaxf(fabsf(s_prop[1]), fabsf(s_prop[2])));
                const float ismax = fmaxf(1.0f / (fabsf(s_prop[3]) + 1e-6f),
                                    fmaxf(1.0f / (fabsf(s_prop[4]) + 1e-6f),
                                          1.0f / (fabsf(s_prop[5]) + 1e-6f)));
                const float B1 = (ptm + cmax) * ismax * s[OFF_STAT] + s[OFF_STAT + 2];
                const float B2 = B1 * s[OFF_STAT + 1] + s[OFF_STAT + 3];
                if (B1 > 16384.0f) {
                    int e; frexpf(B1 * (1.0f / 16384.0f), &e);
                    sc1 = ldexpf(1.0f, -e); inv1 = ldexpf(1.0f, e);
                }
                if (B2 > 16384.0f) {
                    int e; frexpf(B2 * (1.0f / 16384.0f), &e);
                    sc2 = ldexpf(1.0f, -e); inv2 = ldexpf(1.0f, e);
                }
            }

            { const int tp0 = min(128, n);
              do_l1(sc1, 0, (tp0 + 7) & ~7); }
            __syncthreads();

            for (int p0b = 0; p0b < n; p0b += 128) {
                const int tp = min(128, n - p0b);

                // ---- layer 2: fp16 m16n8k16, A=W2 via ldmatrix, B=H1 via ldmatrix ----
                #pragma unroll
                for (int ng = 0; ng < 4; ng++) {
                    const int n0b = 32 * ng;
                    if (n0b >= tp) break;
                    const int ntmax = min(4, (tp - n0b + 7) >> 3);
                    float acc[4][4];
                    #pragma unroll
                    for (int nt = 0; nt < 4; nt++) {
                        acc[nt][0] = 0.f; acc[nt][1] = 0.f; acc[nt][2] = 0.f; acc[nt][3] = 0.f;
                    }
                    const unsigned b2base = lm2off + (unsigned)(n0b * 144);
                    #pragma unroll
                    for (int ks = 0; ks < 4; ks++) {
                        unsigned aw0, aw1, aw2r, aw3;
                        ldsm4(aw0, aw1, aw2r, aw3, aw2 + 32u * ks);
                        unsigned m0, m1, m2, m3, m4, m5, m6, m7;
                        ldsm4(m0, m1, m2, m3, b2base + 32u * ks);
                        if (ntmax > 2)
                            ldsm4(m4, m5, m6, m7, b2base + 32u * ks + 16u * 144u);
                        mma16(acc[0][0], acc[0][1], acc[0][2], acc[0][3], aw0, aw1, aw2r, aw3, m0, m1);
                        if (ntmax > 1)
                            mma16(acc[1][0], acc[1][1], acc[1][2], acc[1][3], aw0, aw1, aw2r, aw3, m2, m3);
                        if (ntmax > 2)
                            mma16(acc[2][0], acc[2][1], acc[2][2], acc[2][3], aw0, aw1, aw2r, aw3, m4, m5);
                        if (ntmax > 3)
                            mma16(acc[3][0], acc[3][1], acc[3][2], acc[3][3], aw0, aw1, aw2r, aw3, m6, m7);
                    }
                    #pragma unroll
                    for (int nt = 0; nt < 4; nt++) {
                        if (nt < ntmax) {
                            const int p0 = n0b + 8 * nt + 2 * tq;
                            __half* r0 = h2h + p0 * H2ROWH;
                            __half* r1 = r0 + H2ROWH;
                            r0[ch2]     = __float2half(fmaxf(fmaf(acc[nt][0], inv1, bb2a), 0.0f) * sc2);
                            r1[ch2]     = __float2half(fmaxf(fmaf(acc[nt][1], inv1, bb2a), 0.0f) * sc2);
                            r0[ch2 + 8] = __float2half(fmaxf(fmaf(acc[nt][2], inv1, bb2b), 0.0f) * sc2);
                            r1[ch2 + 8] = __float2half(fmaxf(fmaf(acc[nt][3], inv1, bb2b), 0.0f) * sc2);
                        }
                    }
                }
                __syncthreads();

                // ---- layer 3: fp16 m16n8k16, warp covers 32 channels in 2 passes ----
                #pragma unroll
                for (int ng = 0; ng < 4; ng++) {
                    const int n0 = 32 * ng;
                    if (n0 >= tp) break;
                    const int ntmax = min(4, (tp - n0 + 7) >> 3);
                    const unsigned b3base = lm3off + (unsigned)(n0 * 272);
                    #pragma unroll
                    for (int cs = 0; cs < 2; cs++) {
                        float acc[4][4];
                        #pragma unroll
                        for (int nt = 0; nt < 4; nt++) {
                            acc[nt][0] = 0.f; acc[nt][1] = 0.f; acc[nt][2] = 0.f; acc[nt][3] = 0.f;
                        }
                        #pragma unroll
                        for (int ks = 0; ks < 8; ks++) {
                            unsigned m0, m1, m2, m3, m4, m5, m6, m7;
                            ldsm4(m0, m1, m2, m3, b3base + 32u * ks);
                            if (ntmax > 2)
                                ldsm4(m4, m5, m6, m7, b3base + 32u * ks + 16u * 272u);
                            const int a0i = 32 * cs + 4 * ks;
                            mma16(acc[0][0], acc[0][1], acc[0][2], acc[0][3],
                                  a3h[a0i], a3h[a0i + 1], a3h[a0i + 2], a3h[a0i + 3], m0, m1);
                            if (ntmax > 1)
                                mma16(acc[1][0], acc[1][1], acc[1][2], acc[1][3],
                                      a3h[a0i], a3h[a0i + 1], a3h[a0i + 2], a3h[a0i + 3], m2, m3);
                            if (ntmax > 2)
                                mma16(acc[2][0], acc[2][1], acc[2][2], acc[2][3],
                                      a3h[a0i], a3h[a0i + 1], a3h[a0i + 2], a3h[a0i + 3], m4, m5);
                            if (ntmax > 3)
                                mma16(acc[3][0], acc[3][1], acc[3][2], acc[3][3],
                                      a3h[a0i], a3h[a0i + 1], a3h[a0i + 2], a3h[a0i + 3], m6, m7);
                        }
                        #pragma unroll
                        for (int nt = 0; nt < 4; nt++) {
                            const int p0 = n0 + 8 * nt + 2 * tq;
                            if (p0 < tp) {
                                chmax[cs][0] = fmaxf(chmax[cs][0], acc[nt][0]);
                                chmax[cs][1] = fmaxf(chmax[cs][1], acc[nt][2]);
                            }
                            if (p0 + 1 < tp) {
                                chmax[cs][0] = fmaxf(chmax[cs][0], acc[nt][1]);
                                chmax[cs][1] = fmaxf(chmax[cs][1], acc[nt][3]);
                            }
                        }
                    }
                }
                if (p0b + 128 < n) {
                    const int tpn = min(128, n - p0b - 128);
                    do_l1(sc1, p0b + 128, (tpn + 7) & ~7);
                    __syncthreads();
                }
            }

            #pragma unroll
            for (int cs = 0; cs < 2; cs++) {
                chmax[cs][0] = fmaxf(chmax[cs][0], __shfl_xor_sync(0xffffffffu, chmax[cs][0], 1));
                chmax[cs][0] = fmaxf(chmax[cs][0], __shfl_xor_sync(0xffffffffu, chmax[cs][0], 2));
                chmax[cs][1] = fmaxf(chmax[cs][1], __shfl_xor_sync(0xffffffffu, chmax[cs][1], 1));
                chmax[cs][1] = fmaxf(chmax[cs][1], __shfl_xor_sync(0xffffffffu, chmax[cs][1], 2));
                if (tq == 0) {
                    const int ch = 32 * w + 16 * cs + g;
                    s[OFF_FEATS + ch]     = chmax[cs][0] * inv2 + b3[ch];
                    s[OFF_FEATS + ch + 8] = chmax[cs][1] * inv2 + b3[ch + 8];
                }
            }
        }

        __syncthreads();   // T1: feats ready; s_pid[par^1] published; buffers free
        const unsigned npid = s_pid[par ^ 1];

        if (w < 7) {
            if (valid) {
                float acc = 0.0f;
                #pragma unroll
                for (int i = 0; i < 8; i++) {
                    const int idx = i * 32 + lane;
                    acc = fmaf(s[OFF_FEATS + idx], s[OFF_WH + w * 256 + idx], acc);
                }
                #pragma unroll
                for (int o = 16; o > 0; o >>= 1)
                    acc += __shfl_xor_sync(0xffffffffu, acc, o);
                if (lane == 0) {
                    if (w == 0) out[pid] = acc + s[OFF_BH];
                    else        out[NP + pid * 6 + (w - 1)] = acc + s[OFF_BH + w];
                }
            } else if (lane == 0) {
                if (w == 0) out[pid] = s[OFF_BH];
                else        out[NP + pid * 6 + (w - 1)] = s[OFF_BH + w];
            }
        } else {
            // warp 7: stage next proposal entirely (prop + count + points + abs-max)
            if (npid < NP) {
                int nn = 0;
                if (lane == 0) nn = __ldg(counts + npid);
                nn = __shfl_sync(0xffffffffu, nn, 0);
                if (lane < 6) s_prop[lane] = __ldg(proposals + (size_t)npid * 6 + lane);
                if (lane == 0) s_ncnt = nn;
                const uint4* gp4 = (const uint4*)(points + (size_t)npid * (MAXNP * 3));
                uint4* sp4 = (uint4*)(s + OFF_PTS);
                const int nf4 = (3 * nn + 3) >> 2;
                float lm = 0.0f;
                for (int i = lane; i < nf4; i += 32) {
                    const uint4 d = __ldg(gp4 + i);
                    sp4[i] = d;
                    lm = fmaxf(lm, fmaxf(fmaxf(fabsf(__uint_as_float(d.x)), fabsf(__uint_as_float(d.y))),
                                         fmaxf(fabsf(__uint_as_float(d.z)), fabsf(__uint_as_float(d.w)))));
                }
                #pragma unroll
                for (int o = 16; o > 0; o >>= 1) lm = fmaxf(lm, __shfl_xor_sync(0xffffffffu, lm, o));
                if (lane < 8) s[OFF_WPM + lane] = lm;
            }
        }
        __syncthreads();   // T2: next proposal staged
        par ^= 1;
    }
}

extern "C" void kernel_launch(void* const* d_in, const int* in_sizes, int n_in,
                              void* d_out, int out_size)
{
    const float* points    = (const float*)d_in[0];
    const int*   counts    = (const int*)  d_in[1];
    const float* proposals = (const float*)d_in[2];
    const float* W1 = (const float*)d_in[3];
    const float* b1 = (const float*)d_in[4];
    const float* W2 = (const float*)d_in[5];
    const float* b2 = (const float*)d_in[6];
    const float* W3 = (const float*)d_in[7];
    const float* b3 = (const float*)d_in[8];
    const float* Wc = (const float*)d_in[9];
    const float* bc = (const float*)d_in[10];
    const float* Wr = (const float*)d_in[11];
    const float* br = (const float*)d_in[12];
    float* out = (float*)d_out;

    int dev = 0, sms = 148;
    cudaGetDevice(&dev);
    cudaDeviceGetAttribute(&sms, cudaDevAttrMultiProcessorCount, dev);
    cudaFuncSetAttribute(refine_kernel,
                         cudaFuncAttributeMaxDynamicSharedMemorySize,
                         SMEM_FLOATS * (int)sizeof(float));

    reset_ticket_kernel<<<1, 1>>>();
    refine_kernel<<<2 * sms, 256, SMEM_FLOATS * (int)sizeof(float)>>>(
        points, counts, proposals, W1, b1, W2, b2, W3, b3, Wc, bc, Wr, br, out);
}